// round 6
// baseline (speedup 1.0000x reference)
#include <cuda_runtime.h>
#include <cuda_bf16.h>
#include <cstdint>

#define Nn   4096
#define Ee   8192
#define INV  512
#define OUTV 512

// HMMA core: 128x128 CTA tile, 512 threads (4x4 warps, 32x32 warp tiles)
// KCH=64, SW128-swizzled 128B rows, 2 stages
#define KCH   64
#define TILB  16384                 // 128 rows * 128 B
#define STGB  (4*TILB)              // Ah,Al,Bh,Bl = 64 KB
#define NSTG  2
#define DSMEM (NSTG*STGB)           // 128 KB (covers 128x129 f32 C = 66048 B)
#define NTHR  512
#define NT2   (Nn/128)
#define NTIL  (NT2*(NT2+1)/2)

__device__ __align__(128) float g_s[Ee];
__device__ __align__(128) __nv_bfloat16 g_TAh[(size_t)Nn*Ee];
__device__ __align__(128) __nv_bfloat16 g_TAl[(size_t)Nn*Ee];
__device__ __align__(128) __nv_bfloat16 g_TBh[(size_t)Nn*Ee];
__device__ __align__(128) __nv_bfloat16 g_TBl[(size_t)Nn*Ee];
__device__ __align__(128) __nv_bfloat16 g_Bh[(size_t)Nn*Nn];
__device__ __align__(128) __nv_bfloat16 g_Bl[(size_t)Nn*Nn];
__device__ __align__(128) float g_Y[(size_t)Nn*OUTV];
__device__ __align__(128) __nv_bfloat16 g_Yth[(size_t)OUTV*Nn];
__device__ __align__(128) __nv_bfloat16 g_Ytl[(size_t)OUTV*Nn];

__device__ __forceinline__ uint32_t smem_u32(const void* p) {
    uint32_t a;
    asm("{ .reg .u64 t; cvta.to.shared.u64 t, %1; cvt.u32.u64 %0, t; }" : "=r"(a) : "l"(p));
    return a;
}
__device__ __forceinline__ uint32_t swz(uint32_t off) {   // SW128: bits[4:6] ^= bits[7:9]
    return off ^ ((off >> 3) & 0x70);
}
__device__ __forceinline__ void cpa16(uint32_t s, const void* g) {
    asm volatile("cp.async.cg.shared.global [%0], [%1], 16;" :: "r"(s), "l"(g));
}
#define CPA_COMMIT() asm volatile("cp.async.commit_group;" ::: "memory")
#define CPA_WAIT1()  asm volatile("cp.async.wait_group 1;" ::: "memory")
#define CPA_WAIT0()  asm volatile("cp.async.wait_group 0;" ::: "memory")

__device__ __forceinline__ void ldsm4(uint32_t a, uint32_t* r) {
    asm volatile("ldmatrix.sync.aligned.m8n8.x4.shared.b16 {%0,%1,%2,%3}, [%4];"
                 : "=r"(r[0]), "=r"(r[1]), "=r"(r[2]), "=r"(r[3]) : "r"(a));
}
__device__ __forceinline__ void mma16816(float* c, const uint32_t* a, const uint32_t* b) {
    asm volatile(
        "mma.sync.aligned.m16n8k16.row.col.f32.bf16.bf16.f32 "
        "{%0,%1,%2,%3}, {%4,%5,%6,%7}, {%8,%9}, {%0,%1,%2,%3};"
        : "+f"(c[0]), "+f"(c[1]), "+f"(c[2]), "+f"(c[3])
        : "r"(a[0]), "r"(a[1]), "r"(a[2]), "r"(a[3]), "r"(b[0]), "r"(b[1]));
}

__device__ __forceinline__ void split1(float x, __nv_bfloat16& h, __nv_bfloat16& l) {
    h = __float2bfloat16_rn(x);
    l = __float2bfloat16_rn(x - __bfloat162float(h));
}
__device__ __forceinline__ void split_pack4(float f0, float f1, float f2, float f3,
                                            uint2& hv, uint2& lv) {
    __nv_bfloat16 h0,h1,h2,h3,l0,l1,l2,l3;
    split1(f0,h0,l0); split1(f1,h1,l1); split1(f2,h2,l2); split1(f3,h3,l3);
    __nv_bfloat162 a = __halves2bfloat162(h0,h1), b = __halves2bfloat162(h2,h3);
    __nv_bfloat162 c = __halves2bfloat162(l0,l1), d = __halves2bfloat162(l2,l3);
    hv.x = *(uint32_t*)&a; hv.y = *(uint32_t*)&b;
    lv.x = *(uint32_t*)&c; lv.y = *(uint32_t*)&d;
}

// Load one 128xKCH chunk (4 tiles) of chunk index c into stage st.
__device__ __forceinline__ void load_chunk(
    uint32_t sb, int st, int c,
    const __nv_bfloat16* Ah, const __nv_bfloat16* Al, size_t lda,
    const __nv_bfloat16* Bh, const __nv_bfloat16* Bl, size_t ldb) {
    const int tid = threadIdx.x;
    uint32_t stb = sb + (uint32_t)st * STGB;
    const __nv_bfloat16* srcs[4] = { Ah, Al, Bh, Bl };
    size_t lds[4] = { lda, lda, ldb, ldb };
#pragma unroll
    for (int t = 0; t < 8; ++t) {
        int idx = tid + t * NTHR;               // 0..4095
        int tile = idx >> 10;                   // 1024 segs per tile
        int row = (idx >> 3) & 127;
        int c16 = idx & 7;
        const __nv_bfloat16* g = srcs[tile] + (size_t)row * lds[tile] + c * KCH + c16 * 8;
        cpa16(stb + tile * TILB + swz(row * 128 + c16 * 16), g);
    }
    CPA_COMMIT();
}

// 2-stage pipelined core, 512 threads; acc[2][4][4]; terms Ah*Bh + Ah*Bl + Al*Bh.
__device__ __forceinline__ void gemm_core(
    uint32_t sb, int nch,
    const __nv_bfloat16* Ah, const __nv_bfloat16* Al, size_t lda,
    const __nv_bfloat16* Bh, const __nv_bfloat16* Bl, size_t ldb,
    float acc[2][4][4]) {
    const int tid = threadIdx.x, wid = tid >> 5, lane = tid & 31;
    const int wm = wid & 3, wn = wid >> 2;

    const int aRow = wm * 32 + (lane & 15);
    const int aColB = (lane >> 4) * 16;          // bytes
    const int g = lane >> 3;
    const int bRow = wn * 32 + (lane & 7) + ((g & 2) ? 8 : 0);
    const int bColB = (g & 1) * 16;              // bytes

    load_chunk(sb, 0, 0, Ah, Al, lda, Bh, Bl, ldb);
    if (nch > 1) load_chunk(sb, 1, 1, Ah, Al, lda, Bh, Bl, ldb);
    else CPA_COMMIT();

    for (int c = 0; c < nch; ++c) {
        CPA_WAIT1();
        __syncthreads();
        uint32_t stb = sb + (uint32_t)(c & 1) * STGB;
#pragma unroll
        for (int ks = 0; ks < 4; ++ks) {
            uint32_t kbB = ks * 32;              // 16 elems per step
            uint32_t afh[2][4], afl[2][4], bfh[2][4], bfl[2][4];
#pragma unroll
            for (int mf = 0; mf < 2; ++mf)
                ldsm4(stb + 0 * TILB + swz((aRow + mf * 16) * 128 + kbB + aColB), afh[mf]);
#pragma unroll
            for (int nf2 = 0; nf2 < 2; ++nf2)
                ldsm4(stb + 2 * TILB + swz((bRow + nf2 * 16) * 128 + kbB + bColB), bfh[nf2]);
#pragma unroll
            for (int mf = 0; mf < 2; ++mf)
#pragma unroll
                for (int nf = 0; nf < 4; ++nf)
                    mma16816(acc[mf][nf], afh[mf], &bfh[nf >> 1][(nf & 1) * 2]);
#pragma unroll
            for (int nf2 = 0; nf2 < 2; ++nf2)
                ldsm4(stb + 3 * TILB + swz((bRow + nf2 * 16) * 128 + kbB + bColB), bfl[nf2]);
#pragma unroll
            for (int mf = 0; mf < 2; ++mf)
#pragma unroll
                for (int nf = 0; nf < 4; ++nf)
                    mma16816(acc[mf][nf], afh[mf], &bfl[nf >> 1][(nf & 1) * 2]);
#pragma unroll
            for (int mf = 0; mf < 2; ++mf)
                ldsm4(stb + 1 * TILB + swz((aRow + mf * 16) * 128 + kbB + aColB), afl[mf]);
#pragma unroll
            for (int mf = 0; mf < 2; ++mf)
#pragma unroll
                for (int nf = 0; nf < 4; ++nf)
                    mma16816(acc[mf][nf], afl[mf], &bfh[nf >> 1][(nf & 1) * 2]);
        }
        __syncthreads();
        if (c + 2 < nch) load_chunk(sb, c & 1, c + 2, Ah, Al, lda, Bh, Bl, ldb);
        else CPA_COMMIT();
    }
    CPA_WAIT0();
}

__device__ __forceinline__ void store_c(float* smC, float acc[2][4][4]) {
    const int tid = threadIdx.x, wid = tid >> 5, lane = tid & 31;
    const int wm = wid & 3, wn = wid >> 2;
#pragma unroll
    for (int mf = 0; mf < 2; ++mf)
#pragma unroll
        for (int nf = 0; nf < 4; ++nf) {
            int r0 = wm * 32 + mf * 16 + (lane >> 2);
            int c0 = wn * 32 + nf * 8 + (lane & 3) * 2;
            smC[r0 * 129 + c0]       = acc[mf][nf][0];
            smC[r0 * 129 + c0 + 1]   = acc[mf][nf][1];
            smC[(r0+8) * 129 + c0]   = acc[mf][nf][2];
            smC[(r0+8) * 129 + c0+1] = acc[mf][nf][3];
        }
}

// ---------------------------------------------------------------------------
__global__ void escale_kernel(const float* __restrict__ He, const float* __restrict__ p) {
    int warp = (blockIdx.x * blockDim.x + threadIdx.x) >> 5;
    int lane = threadIdx.x & 31;
    if (warp >= Ee) return;
    const float* row = He + (size_t)warp * 128;
    float acc = 0.f;
#pragma unroll
    for (int i = 0; i < 4; ++i) acc += row[lane + 32*i] * p[lane + 32*i];
#pragma unroll
    for (int o = 16; o; o >>= 1) acc += __shfl_xor_sync(0xffffffffu, acc, o);
    if (lane == 0) g_s[warp] = acc;
}

__global__ void splitT_kernel(const float* __restrict__ T) {
    size_t i = (size_t)blockIdx.x * blockDim.x + threadIdx.x;
    size_t e = i * 4;
    int k = (int)(e & (Ee - 1));
    float4 x = *(const float4*)(T + e);
    float4 sv = *(const float4*)(g_s + k);
    uint2 hv, lv;
    split_pack4(x.x, x.y, x.z, x.w, hv, lv);
    *(uint2*)(g_TBh + e) = hv; *(uint2*)(g_TBl + e) = lv;
    split_pack4(x.x*sv.x, x.y*sv.y, x.z*sv.z, x.w*sv.w, hv, lv);
    *(uint2*)(g_TAh + e) = hv; *(uint2*)(g_TAl + e) = lv;
}

__global__ void splitYt_kernel(const float* __restrict__ Y) {
    __shared__ float t[32][33];
    int kbase = blockIdx.y * 32, nbase = blockIdx.x * 32;
    int tx = threadIdx.x, ty = threadIdx.y;
#pragma unroll
    for (int j = 0; j < 32; j += 8)
        t[ty + j][tx] = Y[(size_t)(kbase + ty + j) * OUTV + nbase + tx];
    __syncthreads();
#pragma unroll
    for (int j = 0; j < 32; j += 8) {
        int n = nbase + ty + j;
        __nv_bfloat16 h, l;
        split1(t[tx][ty + j], h, l);
        g_Yth[(size_t)n * Nn + kbase + tx] = h;
        g_Ytl[(size_t)n * Nn + kbase + tx] = l;
    }
}

// fp32 SIMT SGEMM for Y = H_v @ W (small)
__global__ __launch_bounds__(256, 2) void sgemm_kernel(
    const float* __restrict__ A, const float* __restrict__ Bm,
    float* __restrict__ C, int M, int Ncols, int K) {
    __shared__ float As[16][128];
    __shared__ float Bs[16][128];
    const int tid = threadIdx.x, tx = tid & 15, ty = tid >> 4;
    const int row0 = blockIdx.y * 128, col0 = blockIdx.x * 128;
    float acc[8][8] = {};
    for (int k0 = 0; k0 < K; k0 += 16) {
#pragma unroll
        for (int l = 0; l < 2; ++l) {
            int idx = tid + l * 256;
            int r = idx >> 2, c4 = (idx & 3) * 4;
            float4 v = *(const float4*)&A[(size_t)(row0 + r) * K + k0 + c4];
            As[c4+0][r]=v.x; As[c4+1][r]=v.y; As[c4+2][r]=v.z; As[c4+3][r]=v.w;
            int rb = idx >> 5, cb = (idx & 31) * 4;
            *(float4*)&Bs[rb][cb] = *(const float4*)&Bm[(size_t)(k0+rb)*Ncols + col0 + cb];
        }
        __syncthreads();
#pragma unroll
        for (int kk = 0; kk < 16; ++kk) {
            float a[8], b[8];
            *(float4*)(a) = *(const float4*)&As[kk][ty*8];
            *(float4*)(a+4) = *(const float4*)&As[kk][ty*8+4];
            *(float4*)(b) = *(const float4*)&Bs[kk][tx*8];
            *(float4*)(b+4) = *(const float4*)&Bs[kk][tx*8+4];
#pragma unroll
            for (int i = 0; i < 8; ++i)
#pragma unroll
                for (int j = 0; j < 8; ++j) acc[i][j] = fmaf(a[i], b[j], acc[i][j]);
        }
        __syncthreads();
    }
#pragma unroll
    for (int i = 0; i < 8; ++i)
#pragma unroll
        for (int j = 0; j < 8; ++j)
            C[(size_t)(row0+ty*8+i)*Ncols + col0+tx*8+j] = acc[i][j];
}

// ---------------------------------------------------------------------------
// symmetric big GEMM: persistent CTAs, supergroup tile order
// ---------------------------------------------------------------------------
__global__ __launch_bounds__(NTHR, 1) void symgemm_mma(const float* __restrict__ adjv) {
    extern __shared__ char dynsm[];
    uint32_t sb = smem_u32(dynsm);
    float* smC = (float*)dynsm;
    const int tid = threadIdx.x, wid = tid >> 5, lid = tid & 31;

    for (int tile = blockIdx.x; tile < NTIL; tile += gridDim.x) {
        // decode tile -> (bi,bj): 8x8 super-groups over the upper triangle
        int t = tile, SI = 0, SJ = 0;
        bool found = false;
        for (SI = 0; SI < NT2/8 && !found; ++SI)
            for (SJ = SI; SJ < NT2/8; ++SJ) {
                int sz = (SI == SJ) ? 36 : 64;
                if (t < sz) { found = true; break; }
                t -= sz;
            }
        --SI;
        int bi, bj;
        if (SI == SJ) {
            int li = 0;
            while (t >= 8 - li) { t -= 8 - li; ++li; }
            bi = SI * 8 + li; bj = SJ * 8 + li + t;
        } else {
            bi = SI * 8 + (t >> 3); bj = SJ * 8 + (t & 7);
        }
        const int row0 = bi * 128, col0 = bj * 128;

        float acc[2][4][4] = {};
        gemm_core(sb, Ee / KCH,
                  g_TAh + (size_t)row0 * Ee, g_TAl + (size_t)row0 * Ee, Ee,
                  g_TBh + (size_t)col0 * Ee, g_TBl + (size_t)col0 * Ee, Ee, acc);
        __syncthreads();
        store_c(smC, acc);
        __syncthreads();

        for (int rr = wid; rr < 128; rr += 16) {
            int gi = row0 + rr;
            int cbase = lid << 2;
            float m0 = smC[rr*129 + cbase+0], m1 = smC[rr*129 + cbase+1];
            float m2 = smC[rr*129 + cbase+2], m3 = smC[rr*129 + cbase+3];
            if (bi == bj) {
                int jb = rr - cbase;
                if (jb == 0) m0 = 1.f; else if (jb == 1) m1 = 1.f;
                else if (jb == 2) m2 = 1.f; else if (jb == 3) m3 = 1.f;
            }
            const float4 a4 = *(const float4*)&adjv[(size_t)gi * Nn + col0 + cbase];
            uint2 hv, lv;
            split_pack4((m0+1.f)*a4.x, (m1+1.f)*a4.y, (m2+1.f)*a4.z, (m3+1.f)*a4.w, hv, lv);
            size_t o = (size_t)gi * Nn + col0 + cbase;
            *(uint2*)(g_Bh + o) = hv; *(uint2*)(g_Bl + o) = lv;
        }
        if (bi != bj) {
            for (int cc = wid; cc < 128; cc += 16) {
                int gj = col0 + cc;
                int rbase = lid << 2;
                float m0 = smC[(rbase+0)*129 + cc], m1 = smC[(rbase+1)*129 + cc];
                float m2 = smC[(rbase+2)*129 + cc], m3 = smC[(rbase+3)*129 + cc];
                const float4 a4 = *(const float4*)&adjv[(size_t)gj * Nn + row0 + rbase];
                uint2 hv, lv;
                split_pack4((m0+1.f)*a4.x, (m1+1.f)*a4.y, (m2+1.f)*a4.z, (m3+1.f)*a4.w, hv, lv);
                size_t o = (size_t)gj * Nn + row0 + rbase;
                *(uint2*)(g_Bh + o) = hv; *(uint2*)(g_Bl + o) = lv;
            }
        }
        __syncthreads();
    }
}

// ---------------------------------------------------------------------------
// out = 0.5 * B @ Y + bias
// ---------------------------------------------------------------------------
__global__ __launch_bounds__(NTHR, 1) void outgemm_mma(const float* __restrict__ bias,
                                                       float* __restrict__ outp) {
    extern __shared__ char dynsm[];
    uint32_t sb = smem_u32(dynsm);
    float* smC = (float*)dynsm;
    const int tid = threadIdx.x, wid = tid >> 5, lid = tid & 31;

    const int bi = blockIdx.x >> 2, bj = blockIdx.x & 3;
    const int row0 = bi * 128, col0 = bj * 128;

    float acc[2][4][4] = {};
    gemm_core(sb, Nn / KCH,
              g_Bh + (size_t)row0 * Nn, g_Bl + (size_t)row0 * Nn, Nn,
              g_Yth + (size_t)col0 * Nn, g_Ytl + (size_t)col0 * Nn, Nn, acc);
    __syncthreads();
    store_c(smC, acc);
    __syncthreads();

    for (int rr = wid; rr < 128; rr += 16) {
        int gi = row0 + rr;
        int cbase = lid << 2;
        const float4 b4 = *(const float4*)&bias[col0 + cbase];
        float4 o4 = { 0.5f*smC[rr*129+cbase+0] + b4.x, 0.5f*smC[rr*129+cbase+1] + b4.y,
                      0.5f*smC[rr*129+cbase+2] + b4.z, 0.5f*smC[rr*129+cbase+3] + b4.w };
        *(float4*)&outp[(size_t)gi * OUTV + col0 + cbase] = o4;
    }
}

__global__ void copy_kernel(const float* __restrict__ s, float* __restrict__ d, int n4) {
    int i = blockIdx.x * blockDim.x + threadIdx.x;
    if (i < n4) ((float4*)d)[i] = ((const float4*)s)[i];
}

extern "C" void kernel_launch(void* const* d_in, const int* in_sizes, int n_in,
                              void* d_out, int out_size) {
    const float* H_v   = (const float*)d_in[0];
    const float* H_e   = (const float*)d_in[1];
    const float* adj_v = (const float*)d_in[3];
    const float* T     = (const float*)d_in[4];
    const float* W     = (const float*)d_in[5];
    const float* p     = (const float*)d_in[6];
    const float* bias  = (const float*)d_in[7];
    float* out = (float*)d_out;

    float* Y_ptr;
    cudaGetSymbolAddress((void**)&Y_ptr, g_Y);
    cudaFuncSetAttribute(symgemm_mma, cudaFuncAttributeMaxDynamicSharedMemorySize, DSMEM);
    cudaFuncSetAttribute(outgemm_mma, cudaFuncAttributeMaxDynamicSharedMemorySize, DSMEM);

    escale_kernel<<<Ee / 8, 256>>>(H_e, p);
    splitT_kernel<<<(int)(((size_t)Nn * Ee / 4) / 256), 256>>>(T);
    sgemm_kernel<<<dim3(OUTV / 128, Nn / 128), 256>>>(H_v, W, Y_ptr, Nn, OUTV, INV);
    splitYt_kernel<<<dim3(OUTV / 32, Nn / 32), dim3(32, 8)>>>(Y_ptr);
    symgemm_mma<<<148, NTHR, DSMEM>>>(adj_v);
    outgemm_mma<<<128, NTHR, DSMEM>>>(bias, out);

    if (out_size >= Nn * OUTV + Ee * 128) {
        int n4 = (Ee * 128) / 4;
        copy_kernel<<<(n4 + 255) / 256, 256>>>(H_e, out + (size_t)Nn * OUTV, n4);
    }
}

// round 7
// speedup vs baseline: 1.1957x; 1.1957x over previous
#include <cuda_runtime.h>
#include <cuda_bf16.h>
#include <cstdint>

#define Nn   4096
#define Ee   8192
#define INV  512
#define OUTV 512

// HMMA GEMM geometry: 128x128 CTA tile, KCH=32, SW64-swizzled 64B rows (R5 core)
#define KCH   32
#define TILB  8192                  // 128 rows * 64 B
#define STGB  (4*TILB)              // 4 tiles (Ah,Al,Bh,Bl) = 32 KB
#define NSTG  3
#define DSMEM (NSTG*STGB)           // 96 KB (also covers 128x129 f32 C = 66048 B)
#define NT2   (Nn/128)
#define NTIL  (NT2*(NT2+1)/2)

__device__ __align__(128) float g_s[Ee];
__device__ __align__(128) __nv_bfloat16 g_TAh[(size_t)Nn*Ee];
__device__ __align__(128) __nv_bfloat16 g_TAl[(size_t)Nn*Ee];
__device__ __align__(128) __nv_bfloat16 g_TBh[(size_t)Nn*Ee];
__device__ __align__(128) __nv_bfloat16 g_TBl[(size_t)Nn*Ee];
__device__ __align__(128) __nv_bfloat16 g_Bh[(size_t)Nn*Nn];
__device__ __align__(128) __nv_bfloat16 g_Bl[(size_t)Nn*Nn];
__device__ __align__(128) float g_Y[(size_t)Nn*OUTV];
__device__ __align__(128) __nv_bfloat16 g_Yth[(size_t)OUTV*Nn];
__device__ __align__(128) __nv_bfloat16 g_Ytl[(size_t)OUTV*Nn];

__device__ __forceinline__ uint32_t smem_u32(const void* p) {
    uint32_t a;
    asm("{ .reg .u64 t; cvta.to.shared.u64 t, %1; cvt.u32.u64 %0, t; }" : "=r"(a) : "l"(p));
    return a;
}
__device__ __forceinline__ uint32_t swz(uint32_t off) {     // SW64: bits[4:5] ^= bits[7:8]
    return off ^ ((off >> 3) & 0x30);
}
__device__ __forceinline__ void cpa16(uint32_t s, const void* g) {
    asm volatile("cp.async.cg.shared.global [%0], [%1], 16;" :: "r"(s), "l"(g));
}
#define CPA_COMMIT() asm volatile("cp.async.commit_group;" ::: "memory")
#define CPA_WAIT2()  asm volatile("cp.async.wait_group 2;" ::: "memory")
#define CPA_WAIT0()  asm volatile("cp.async.wait_group 0;" ::: "memory")

__device__ __forceinline__ void ldsm4(uint32_t a, uint32_t* r) {
    asm volatile("ldmatrix.sync.aligned.m8n8.x4.shared.b16 {%0,%1,%2,%3}, [%4];"
                 : "=r"(r[0]), "=r"(r[1]), "=r"(r[2]), "=r"(r[3]) : "r"(a));
}
__device__ __forceinline__ void mma16816(float* c, const uint32_t* a, const uint32_t* b) {
    asm volatile(
        "mma.sync.aligned.m16n8k16.row.col.f32.bf16.bf16.f32 "
        "{%0,%1,%2,%3}, {%4,%5,%6,%7}, {%8,%9}, {%0,%1,%2,%3};"
        : "+f"(c[0]), "+f"(c[1]), "+f"(c[2]), "+f"(c[3])
        : "r"(a[0]), "r"(a[1]), "r"(a[2]), "r"(a[3]), "r"(b[0]), "r"(b[1]));
}

__device__ __forceinline__ void split1(float x, __nv_bfloat16& h, __nv_bfloat16& l) {
    h = __float2bfloat16_rn(x);
    l = __float2bfloat16_rn(x - __bfloat162float(h));
}
__device__ __forceinline__ void split_pack4(float f0, float f1, float f2, float f3,
                                            uint2& hv, uint2& lv) {
    __nv_bfloat16 h0,h1,h2,h3,l0,l1,l2,l3;
    split1(f0,h0,l0); split1(f1,h1,l1); split1(f2,h2,l2); split1(f3,h3,l3);
    __nv_bfloat162 a = __halves2bfloat162(h0,h1), b = __halves2bfloat162(h2,h3);
    __nv_bfloat162 c = __halves2bfloat162(l0,l1), d = __halves2bfloat162(l2,l3);
    hv.x = *(uint32_t*)&a; hv.y = *(uint32_t*)&b;
    lv.x = *(uint32_t*)&c; lv.y = *(uint32_t*)&d;
}

// Load one 128xKCH chunk (4 tiles) of chunk index c into stage st (SW64 layout).
__device__ __forceinline__ void load_chunk(
    uint32_t sb, int st, int c,
    const __nv_bfloat16* Ah, const __nv_bfloat16* Al, size_t lda,
    const __nv_bfloat16* Bh, const __nv_bfloat16* Bl, size_t ldb) {
    const int tid = threadIdx.x;
    uint32_t stb = sb + (uint32_t)st * STGB;
    const __nv_bfloat16* srcs[4] = { Ah, Al, Bh, Bl };
    size_t lds[4] = { lda, lda, ldb, ldb };
#pragma unroll
    for (int tile = 0; tile < 4; ++tile) {
#pragma unroll
        for (int t = 0; t < 2; ++t) {
            int idx = tid + t * 256;             // 0..511
            int row = idx >> 2, c16 = idx & 3;
            const __nv_bfloat16* g = srcs[tile] + (size_t)row * lds[tile] + c * KCH + c16 * 8;
            cpa16(stb + tile * TILB + swz(row * 64 + c16 * 16), g);
        }
    }
    CPA_COMMIT();
}

// 3-stage pipelined core; acc[4][4][4]; 3-term split (Ah*Bh + Ah*Bl + Al*Bh). (R5)
__device__ __forceinline__ void gemm_core(
    uint32_t sb, int nch,
    const __nv_bfloat16* Ah, const __nv_bfloat16* Al, size_t lda,
    const __nv_bfloat16* Bh, const __nv_bfloat16* Bl, size_t ldb,
    float acc[4][4][4]) {
    const int tid = threadIdx.x, wid = tid >> 5, lane = tid & 31;
    const int wm = wid & 1, wn = wid >> 1;

    const int aRow = wm * 64 + (lane & 15);
    const int aCol = (lane >> 4) * 16;
    const int g = lane >> 3;
    const int bRow = wn * 32 + (lane & 7) + ((g & 2) ? 8 : 0);
    const int bCol = (g & 1) * 16;

    load_chunk(sb, 0, 0, Ah, Al, lda, Bh, Bl, ldb);
    load_chunk(sb, 1, 1, Ah, Al, lda, Bh, Bl, ldb);
    load_chunk(sb, 2, 2, Ah, Al, lda, Bh, Bl, ldb);

    int st = 0;
    for (int c = 0; c < nch; ++c) {
        CPA_WAIT2();
        __syncthreads();
        uint32_t stb = sb + (uint32_t)st * STGB;
#pragma unroll
        for (int ks = 0; ks < 2; ++ks) {
            uint32_t kb = ks * 32;
            uint32_t afh[4][4], afl[4][4], bfh[2][4], bfl[2][4];
#pragma unroll
            for (int mf = 0; mf < 4; ++mf)
                ldsm4(stb + 0 * TILB + swz((aRow + mf * 16) * 64 + kb + aCol), afh[mf]);
#pragma unroll
            for (int nf2 = 0; nf2 < 2; ++nf2)
                ldsm4(stb + 2 * TILB + swz((bRow + nf2 * 16) * 64 + kb + bCol), bfh[nf2]);
#pragma unroll
            for (int mf = 0; mf < 4; ++mf)
#pragma unroll
                for (int nf = 0; nf < 4; ++nf)
                    mma16816(acc[mf][nf], afh[mf], &bfh[nf >> 1][(nf & 1) * 2]);
#pragma unroll
            for (int nf2 = 0; nf2 < 2; ++nf2)
                ldsm4(stb + 3 * TILB + swz((bRow + nf2 * 16) * 64 + kb + bCol), bfl[nf2]);
#pragma unroll
            for (int mf = 0; mf < 4; ++mf)
#pragma unroll
                for (int nf = 0; nf < 4; ++nf)
                    mma16816(acc[mf][nf], afh[mf], &bfl[nf >> 1][(nf & 1) * 2]);
#pragma unroll
            for (int mf = 0; mf < 4; ++mf)
                ldsm4(stb + 1 * TILB + swz((aRow + mf * 16) * 64 + kb + aCol), afl[mf]);
#pragma unroll
            for (int mf = 0; mf < 4; ++mf)
#pragma unroll
                for (int nf = 0; nf < 4; ++nf)
                    mma16816(acc[mf][nf], afl[mf], &bfh[nf >> 1][(nf & 1) * 2]);
        }
        __syncthreads();
        if (c + 3 < nch) load_chunk(sb, st, c + 3, Ah, Al, lda, Bh, Bl, ldb);
        else CPA_COMMIT();
        st = (st + 1 == NSTG) ? 0 : st + 1;
    }
    CPA_WAIT0();
}

__device__ __forceinline__ void store_c(float* smC, float acc[4][4][4]) {
    const int tid = threadIdx.x, wid = tid >> 5, lane = tid & 31;
    const int wm = wid & 1, wn = wid >> 1;
#pragma unroll
    for (int mf = 0; mf < 4; ++mf)
#pragma unroll
        for (int nf = 0; nf < 4; ++nf) {
            int r0 = wm * 64 + mf * 16 + (lane >> 2);
            int c0 = wn * 32 + nf * 8 + (lane & 3) * 2;
            smC[r0 * 129 + c0]       = acc[mf][nf][0];
            smC[r0 * 129 + c0 + 1]   = acc[mf][nf][1];
            smC[(r0+8) * 129 + c0]   = acc[mf][nf][2];
            smC[(r0+8) * 129 + c0+1] = acc[mf][nf][3];
        }
}

// ---------------------------------------------------------------------------
__global__ void escale_kernel(const float* __restrict__ He, const float* __restrict__ p) {
    int warp = (blockIdx.x * blockDim.x + threadIdx.x) >> 5;
    int lane = threadIdx.x & 31;
    if (warp >= Ee) return;
    const float* row = He + (size_t)warp * 128;
    float acc = 0.f;
#pragma unroll
    for (int i = 0; i < 4; ++i) acc += row[lane + 32*i] * p[lane + 32*i];
#pragma unroll
    for (int o = 16; o; o >>= 1) acc += __shfl_xor_sync(0xffffffffu, acc, o);
    if (lane == 0) g_s[warp] = acc;
}

__global__ void splitT_kernel(const float* __restrict__ T) {
    size_t i = (size_t)blockIdx.x * blockDim.x + threadIdx.x;
    size_t e = i * 4;
    int k = (int)(e & (Ee - 1));
    float4 x = *(const float4*)(T + e);
    float4 sv = *(const float4*)(g_s + k);
    uint2 hv, lv;
    split_pack4(x.x, x.y, x.z, x.w, hv, lv);
    *(uint2*)(g_TBh + e) = hv; *(uint2*)(g_TBl + e) = lv;
    split_pack4(x.x*sv.x, x.y*sv.y, x.z*sv.z, x.w*sv.w, hv, lv);
    *(uint2*)(g_TAh + e) = hv; *(uint2*)(g_TAl + e) = lv;
}

__global__ void splitYt_kernel(const float* __restrict__ Y) {
    __shared__ float t[32][33];
    int kbase = blockIdx.y * 32, nbase = blockIdx.x * 32;
    int tx = threadIdx.x, ty = threadIdx.y;
#pragma unroll
    for (int j = 0; j < 32; j += 8)
        t[ty + j][tx] = Y[(size_t)(kbase + ty + j) * OUTV + nbase + tx];
    __syncthreads();
#pragma unroll
    for (int j = 0; j < 32; j += 8) {
        int n = nbase + ty + j;
        __nv_bfloat16 h, l;
        split1(t[tx][ty + j], h, l);
        g_Yth[(size_t)n * Nn + kbase + tx] = h;
        g_Ytl[(size_t)n * Nn + kbase + tx] = l;
    }
}

// fp32 SIMT SGEMM for Y = H_v @ W (small)
__global__ __launch_bounds__(256, 2) void sgemm_kernel(
    const float* __restrict__ A, const float* __restrict__ Bm,
    float* __restrict__ C, int M, int Ncols, int K) {
    __shared__ float As[16][128];
    __shared__ float Bs[16][128];
    const int tid = threadIdx.x, tx = tid & 15, ty = tid >> 4;
    const int row0 = blockIdx.y * 128, col0 = blockIdx.x * 128;
    float acc[8][8] = {};
    for (int k0 = 0; k0 < K; k0 += 16) {
#pragma unroll
        for (int l = 0; l < 2; ++l) {
            int idx = tid + l * 256;
            int r = idx >> 2, c4 = (idx & 3) * 4;
            float4 v = *(const float4*)&A[(size_t)(row0 + r) * K + k0 + c4];
            As[c4+0][r]=v.x; As[c4+1][r]=v.y; As[c4+2][r]=v.z; As[c4+3][r]=v.w;
            int rb = idx >> 5, cb = (idx & 31) * 4;
            *(float4*)&Bs[rb][cb] = *(const float4*)&Bm[(size_t)(k0+rb)*Ncols + col0 + cb];
        }
        __syncthreads();
#pragma unroll
        for (int kk = 0; kk < 16; ++kk) {
            float a[8], b[8];
            *(float4*)(a) = *(const float4*)&As[kk][ty*8];
            *(float4*)(a+4) = *(const float4*)&As[kk][ty*8+4];
            *(float4*)(b) = *(const float4*)&Bs[kk][tx*8];
            *(float4*)(b+4) = *(const float4*)&Bs[kk][tx*8+4];
#pragma unroll
            for (int i = 0; i < 8; ++i)
#pragma unroll
                for (int j = 0; j < 8; ++j) acc[i][j] = fmaf(a[i], b[j], acc[i][j]);
        }
        __syncthreads();
    }
#pragma unroll
    for (int i = 0; i < 8; ++i)
#pragma unroll
        for (int j = 0; j < 8; ++j)
            C[(size_t)(row0+ty*8+i)*Ncols + col0+tx*8+j] = acc[i][j];
}

// ---------------------------------------------------------------------------
// symmetric big GEMM: R5 core + persistent CTAs (2/SM) + supergroup order
// ---------------------------------------------------------------------------
__global__ __launch_bounds__(256, 2) void symgemm_mma(const float* __restrict__ adjv) {
    extern __shared__ char dynsm[];
    uint32_t sb = smem_u32(dynsm);
    float* smC = (float*)dynsm;
    const int tid = threadIdx.x, wid = tid >> 5, lid = tid & 31;

    for (int tile = blockIdx.x; tile < NTIL; tile += gridDim.x) {
        // decode tile -> (bi,bj): 8x8 super-groups over the upper triangle
        int t = tile, SI = 0, SJ = 0;
        bool found = false;
        for (SI = 0; SI < NT2/8 && !found; ++SI)
            for (SJ = SI; SJ < NT2/8; ++SJ) {
                int sz = (SI == SJ) ? 36 : 64;
                if (t < sz) { found = true; break; }
                t -= sz;
            }
        --SI;
        int bi, bj;
        if (SI == SJ) {
            int li = 0;
            while (t >= 8 - li) { t -= 8 - li; ++li; }
            bi = SI * 8 + li; bj = SJ * 8 + li + t;
        } else {
            bi = SI * 8 + (t >> 3); bj = SJ * 8 + (t & 7);
        }
        const int row0 = bi * 128, col0 = bj * 128;

        float acc[4][4][4] = {};
        gemm_core(sb, Ee / KCH,
                  g_TAh + (size_t)row0 * Ee, g_TAl + (size_t)row0 * Ee, Ee,
                  g_TBh + (size_t)col0 * Ee, g_TBl + (size_t)col0 * Ee, Ee, acc);
        __syncthreads();
        store_c(smC, acc);
        __syncthreads();

        for (int rr = wid; rr < 128; rr += 8) {
            int gi = row0 + rr;
            int cbase = lid << 2;
            float m0 = smC[rr*129 + cbase+0], m1 = smC[rr*129 + cbase+1];
            float m2 = smC[rr*129 + cbase+2], m3 = smC[rr*129 + cbase+3];
            if (bi == bj) {
                int jb = rr - cbase;
                if (jb == 0) m0 = 1.f; else if (jb == 1) m1 = 1.f;
                else if (jb == 2) m2 = 1.f; else if (jb == 3) m3 = 1.f;
            }
            const float4 a4 = *(const float4*)&adjv[(size_t)gi * Nn + col0 + cbase];
            uint2 hv, lv;
            split_pack4((m0+1.f)*a4.x, (m1+1.f)*a4.y, (m2+1.f)*a4.z, (m3+1.f)*a4.w, hv, lv);
            size_t o = (size_t)gi * Nn + col0 + cbase;
            *(uint2*)(g_Bh + o) = hv; *(uint2*)(g_Bl + o) = lv;
        }
        if (bi != bj) {
            for (int cc = wid; cc < 128; cc += 8) {
                int gj = col0 + cc;
                int rbase = lid << 2;
                float m0 = smC[(rbase+0)*129 + cc], m1 = smC[(rbase+1)*129 + cc];
                float m2 = smC[(rbase+2)*129 + cc], m3 = smC[(rbase+3)*129 + cc];
                const float4 a4 = *(const float4*)&adjv[(size_t)gj * Nn + row0 + rbase];
                uint2 hv, lv;
                split_pack4((m0+1.f)*a4.x, (m1+1.f)*a4.y, (m2+1.f)*a4.z, (m3+1.f)*a4.w, hv, lv);
                size_t o = (size_t)gj * Nn + row0 + rbase;
                *(uint2*)(g_Bh + o) = hv; *(uint2*)(g_Bl + o) = lv;
            }
        }
        __syncthreads();   // smC reads done before next tile's loads reuse smem
    }
}

// ---------------------------------------------------------------------------
// out = 0.5 * B @ Y + bias  (R5 config)
// ---------------------------------------------------------------------------
__global__ __launch_bounds__(256, 2) void outgemm_mma(const float* __restrict__ bias,
                                                      float* __restrict__ outp) {
    extern __shared__ char dynsm[];
    uint32_t sb = smem_u32(dynsm);
    float* smC = (float*)dynsm;
    const int tid = threadIdx.x, wid = tid >> 5, lid = tid & 31;

    const int bi = blockIdx.x >> 2, bj = blockIdx.x & 3;
    const int row0 = bi * 128, col0 = bj * 128;

    float acc[4][4][4] = {};
    gemm_core(sb, Nn / KCH,
              g_Bh + (size_t)row0 * Nn, g_Bl + (size_t)row0 * Nn, Nn,
              g_Yth + (size_t)col0 * Nn, g_Ytl + (size_t)col0 * Nn, Nn, acc);
    __syncthreads();
    store_c(smC, acc);
    __syncthreads();

    for (int rr = wid; rr < 128; rr += 8) {
        int gi = row0 + rr;
        int cbase = lid << 2;
        const float4 b4 = *(const float4*)&bias[col0 + cbase];
        float4 o4 = { 0.5f*smC[rr*129+cbase+0] + b4.x, 0.5f*smC[rr*129+cbase+1] + b4.y,
                      0.5f*smC[rr*129+cbase+2] + b4.z, 0.5f*smC[rr*129+cbase+3] + b4.w };
        *(float4*)&outp[(size_t)gi * OUTV + col0 + cbase] = o4;
    }
}

__global__ void copy_kernel(const float* __restrict__ s, float* __restrict__ d, int n4) {
    int i = blockIdx.x * blockDim.x + threadIdx.x;
    if (i < n4) ((float4*)d)[i] = ((const float4*)s)[i];
}

extern "C" void kernel_launch(void* const* d_in, const int* in_sizes, int n_in,
                              void* d_out, int out_size) {
    const float* H_v   = (const float*)d_in[0];
    const float* H_e   = (const float*)d_in[1];
    const float* adj_v = (const float*)d_in[3];
    const float* T     = (const float*)d_in[4];
    const float* W     = (const float*)d_in[5];
    const float* p     = (const float*)d_in[6];
    const float* bias  = (const float*)d_in[7];
    float* out = (float*)d_out;

    float* Y_ptr;
    cudaGetSymbolAddress((void**)&Y_ptr, g_Y);
    cudaFuncSetAttribute(symgemm_mma, cudaFuncAttributeMaxDynamicSharedMemorySize, DSMEM);
    cudaFuncSetAttribute(outgemm_mma, cudaFuncAttributeMaxDynamicSharedMemorySize, DSMEM);

    escale_kernel<<<Ee / 8, 256>>>(H_e, p);
    splitT_kernel<<<(int)(((size_t)Nn * Ee / 4) / 256), 256>>>(T);
    sgemm_kernel<<<dim3(OUTV / 128, Nn / 128), 256>>>(H_v, W, Y_ptr, Nn, OUTV, INV);
    splitYt_kernel<<<dim3(OUTV / 32, Nn / 32), dim3(32, 8)>>>(Y_ptr);
    symgemm_mma<<<296, 256, DSMEM>>>(adj_v);
    outgemm_mma<<<128, 256, DSMEM>>>(bias, out);

    if (out_size >= Nn * OUTV + Ee * 128) {
        int n4 = (Ee * 128) / 4;
        copy_kernel<<<(n4 + 255) / 256, 256>>>(H_e, out + (size_t)Nn * OUTV, n4);
    }
}

// round 8
// speedup vs baseline: 1.2672x; 1.0598x over previous
#include <cuda_runtime.h>
#include <cuda_bf16.h>
#include <cstdint>

#define Nn   4096
#define Ee   8192
#define INV  512
#define OUTV 512

// HMMA GEMM geometry: 128x128 CTA tile, KCH=32, SW64-swizzled 64B rows (R5 core)
#define KCH   32
#define TILB  8192                  // 128 rows * 64 B
#define STGB  (4*TILB)              // 4 tiles (Ah,Al,Bh,Bl) = 32 KB
#define NSTG  3
#define DSMEM (NSTG*STGB)           // 96 KB (also covers 128x129 f32 C = 66048 B)
#define NT2   (Nn/128)
#define NTIL  (NT2*(NT2+1)/2)

__device__ __align__(128) float g_s[Ee];
__device__ __align__(128) __nv_bfloat16 g_TAh[(size_t)Nn*Ee];
__device__ __align__(128) __nv_bfloat16 g_TAl[(size_t)Nn*Ee];
__device__ __align__(128) __nv_bfloat16 g_TBh[(size_t)Nn*Ee];
__device__ __align__(128) __nv_bfloat16 g_TBl[(size_t)Nn*Ee];
__device__ __align__(128) __nv_bfloat16 g_Bh[(size_t)Nn*Nn];
__device__ __align__(128) __nv_bfloat16 g_Bl[(size_t)Nn*Nn];
__device__ __align__(128) __nv_bfloat16 g_Hh[(size_t)Nn*INV];
__device__ __align__(128) __nv_bfloat16 g_Hl[(size_t)Nn*INV];
__device__ __align__(128) __nv_bfloat16 g_Wth[(size_t)OUTV*INV];
__device__ __align__(128) __nv_bfloat16 g_Wtl[(size_t)OUTV*INV];
__device__ __align__(128) __nv_bfloat16 g_Yth[(size_t)OUTV*Nn];
__device__ __align__(128) __nv_bfloat16 g_Ytl[(size_t)OUTV*Nn];

__device__ __forceinline__ uint32_t smem_u32(const void* p) {
    uint32_t a;
    asm("{ .reg .u64 t; cvta.to.shared.u64 t, %1; cvt.u32.u64 %0, t; }" : "=r"(a) : "l"(p));
    return a;
}
__device__ __forceinline__ uint32_t swz(uint32_t off) {     // SW64: bits[4:5] ^= bits[7:8]
    return off ^ ((off >> 3) & 0x30);
}
__device__ __forceinline__ void cpa16(uint32_t s, const void* g) {
    asm volatile("cp.async.cg.shared.global [%0], [%1], 16;" :: "r"(s), "l"(g));
}
#define CPA_COMMIT() asm volatile("cp.async.commit_group;" ::: "memory")
#define CPA_WAIT2()  asm volatile("cp.async.wait_group 2;" ::: "memory")
#define CPA_WAIT0()  asm volatile("cp.async.wait_group 0;" ::: "memory")

__device__ __forceinline__ void ldsm4(uint32_t a, uint32_t* r) {
    asm volatile("ldmatrix.sync.aligned.m8n8.x4.shared.b16 {%0,%1,%2,%3}, [%4];"
                 : "=r"(r[0]), "=r"(r[1]), "=r"(r[2]), "=r"(r[3]) : "r"(a));
}
__device__ __forceinline__ void mma16816(float* c, const uint32_t* a, const uint32_t* b) {
    asm volatile(
        "mma.sync.aligned.m16n8k16.row.col.f32.bf16.bf16.f32 "
        "{%0,%1,%2,%3}, {%4,%5,%6,%7}, {%8,%9}, {%0,%1,%2,%3};"
        : "+f"(c[0]), "+f"(c[1]), "+f"(c[2]), "+f"(c[3])
        : "r"(a[0]), "r"(a[1]), "r"(a[2]), "r"(a[3]), "r"(b[0]), "r"(b[1]));
}

__device__ __forceinline__ void split1(float x, __nv_bfloat16& h, __nv_bfloat16& l) {
    h = __float2bfloat16_rn(x);
    l = __float2bfloat16_rn(x - __bfloat162float(h));
}
__device__ __forceinline__ void split_pack4(float f0, float f1, float f2, float f3,
                                            uint2& hv, uint2& lv) {
    __nv_bfloat16 h0,h1,h2,h3,l0,l1,l2,l3;
    split1(f0,h0,l0); split1(f1,h1,l1); split1(f2,h2,l2); split1(f3,h3,l3);
    __nv_bfloat162 a = __halves2bfloat162(h0,h1), b = __halves2bfloat162(h2,h3);
    __nv_bfloat162 c = __halves2bfloat162(l0,l1), d = __halves2bfloat162(l2,l3);
    hv.x = *(uint32_t*)&a; hv.y = *(uint32_t*)&b;
    lv.x = *(uint32_t*)&c; lv.y = *(uint32_t*)&d;
}

// Load one 128xKCH chunk (4 tiles) of chunk index c into stage st (SW64 layout).
__device__ __forceinline__ void load_chunk(
    uint32_t sb, int st, int c,
    const __nv_bfloat16* Ah, const __nv_bfloat16* Al, size_t lda,
    const __nv_bfloat16* Bh, const __nv_bfloat16* Bl, size_t ldb) {
    const int tid = threadIdx.x;
    uint32_t stb = sb + (uint32_t)st * STGB;
    const __nv_bfloat16* srcs[4] = { Ah, Al, Bh, Bl };
    size_t lds[4] = { lda, lda, ldb, ldb };
#pragma unroll
    for (int tile = 0; tile < 4; ++tile) {
#pragma unroll
        for (int t = 0; t < 2; ++t) {
            int idx = tid + t * 256;             // 0..511
            int row = idx >> 2, c16 = idx & 3;
            const __nv_bfloat16* g = srcs[tile] + (size_t)row * lds[tile] + c * KCH + c16 * 8;
            cpa16(stb + tile * TILB + swz(row * 64 + c16 * 16), g);
        }
    }
    CPA_COMMIT();
}

// 3-stage pipelined core; acc[4][4][4]; terms ordered Ah*Bh, Al*Bh, Ah*Bl
// (reduces peak live fragment registers vs R5 order).
__device__ __forceinline__ void gemm_core(
    uint32_t sb, int nch,
    const __nv_bfloat16* Ah, const __nv_bfloat16* Al, size_t lda,
    const __nv_bfloat16* Bh, const __nv_bfloat16* Bl, size_t ldb,
    float acc[4][4][4]) {
    const int tid = threadIdx.x, wid = tid >> 5, lane = tid & 31;
    const int wm = wid & 1, wn = wid >> 1;

    const int aRow = wm * 64 + (lane & 15);
    const int aCol = (lane >> 4) * 16;
    const int g = lane >> 3;
    const int bRow = wn * 32 + (lane & 7) + ((g & 2) ? 8 : 0);
    const int bCol = (g & 1) * 16;

    load_chunk(sb, 0, 0, Ah, Al, lda, Bh, Bl, ldb);
    load_chunk(sb, 1, 1, Ah, Al, lda, Bh, Bl, ldb);
    load_chunk(sb, 2, 2, Ah, Al, lda, Bh, Bl, ldb);

    int st = 0;
    for (int c = 0; c < nch; ++c) {
        CPA_WAIT2();
        __syncthreads();
        uint32_t stb = sb + (uint32_t)st * STGB;
#pragma unroll
        for (int ks = 0; ks < 2; ++ks) {
            uint32_t kb = ks * 32;
            uint32_t afh[4][4], afl[4][4], bfh[2][4], bfl[2][4];
#pragma unroll
            for (int mf = 0; mf < 4; ++mf)
                ldsm4(stb + 0 * TILB + swz((aRow + mf * 16) * 64 + kb + aCol), afh[mf]);
#pragma unroll
            for (int nf2 = 0; nf2 < 2; ++nf2)
                ldsm4(stb + 2 * TILB + swz((bRow + nf2 * 16) * 64 + kb + bCol), bfh[nf2]);
#pragma unroll
            for (int mf = 0; mf < 4; ++mf)
#pragma unroll
                for (int nf = 0; nf < 4; ++nf)
                    mma16816(acc[mf][nf], afh[mf], &bfh[nf >> 1][(nf & 1) * 2]);
#pragma unroll
            for (int mf = 0; mf < 4; ++mf)
                ldsm4(stb + 1 * TILB + swz((aRow + mf * 16) * 64 + kb + aCol), afl[mf]);
#pragma unroll
            for (int mf = 0; mf < 4; ++mf)
#pragma unroll
                for (int nf = 0; nf < 4; ++nf)
                    mma16816(acc[mf][nf], afl[mf], &bfh[nf >> 1][(nf & 1) * 2]);
#pragma unroll
            for (int nf2 = 0; nf2 < 2; ++nf2)
                ldsm4(stb + 3 * TILB + swz((bRow + nf2 * 16) * 64 + kb + bCol), bfl[nf2]);
#pragma unroll
            for (int mf = 0; mf < 4; ++mf)
#pragma unroll
                for (int nf = 0; nf < 4; ++nf)
                    mma16816(acc[mf][nf], afh[mf], &bfl[nf >> 1][(nf & 1) * 2]);
        }
        __syncthreads();
        if (c + 3 < nch) load_chunk(sb, st, c + 3, Ah, Al, lda, Bh, Bl, ldb);
        else CPA_COMMIT();
        st = (st + 1 == NSTG) ? 0 : st + 1;
    }
    CPA_WAIT0();
}

__device__ __forceinline__ void store_c(float* smC, float acc[4][4][4]) {
    const int tid = threadIdx.x, wid = tid >> 5, lane = tid & 31;
    const int wm = wid & 1, wn = wid >> 1;
#pragma unroll
    for (int mf = 0; mf < 4; ++mf)
#pragma unroll
        for (int nf = 0; nf < 4; ++nf) {
            int r0 = wm * 64 + mf * 16 + (lane >> 2);
            int c0 = wn * 32 + nf * 8 + (lane & 3) * 2;
            smC[r0 * 129 + c0]       = acc[mf][nf][0];
            smC[r0 * 129 + c0 + 1]   = acc[mf][nf][1];
            smC[(r0+8) * 129 + c0]   = acc[mf][nf][2];
            smC[(r0+8) * 129 + c0+1] = acc[mf][nf][3];
        }
}

// ---------------------------------------------------------------------------
__global__ void escale_kernel(const float* __restrict__ He, const float* __restrict__ p) {
    int warp = (blockIdx.x * blockDim.x + threadIdx.x) >> 5;
    int lane = threadIdx.x & 31;
    if (warp >= Ee) return;
    const float* row = He + (size_t)warp * 128;
    float acc = 0.f;
#pragma unroll
    for (int i = 0; i < 4; ++i) acc += row[lane + 32*i] * p[lane + 32*i];
#pragma unroll
    for (int o = 16; o; o >>= 1) acc += __shfl_xor_sync(0xffffffffu, acc, o);
    if (lane == 0) g_s[warp] = acc;
}

__global__ void splitT_kernel(const float* __restrict__ T) {
    size_t i = (size_t)blockIdx.x * blockDim.x + threadIdx.x;
    size_t e = i * 4;
    int k = (int)(e & (Ee - 1));
    float4 x = *(const float4*)(T + e);
    float4 sv = *(const float4*)(g_s + k);
    uint2 hv, lv;
    split_pack4(x.x, x.y, x.z, x.w, hv, lv);
    *(uint2*)(g_TBh + e) = hv; *(uint2*)(g_TBl + e) = lv;
    split_pack4(x.x*sv.x, x.y*sv.y, x.z*sv.z, x.w*sv.w, hv, lv);
    *(uint2*)(g_TAh + e) = hv; *(uint2*)(g_TAl + e) = lv;
}

// elementwise split of H_v (4096x512)
__global__ void splitHv_kernel(const float* __restrict__ Hv) {
    size_t i = (size_t)blockIdx.x * blockDim.x + threadIdx.x;
    size_t e = i * 4;
    float4 x = *(const float4*)(Hv + e);
    uint2 hv, lv;
    split_pack4(x.x, x.y, x.z, x.w, hv, lv);
    *(uint2*)(g_Hh + e) = hv; *(uint2*)(g_Hl + e) = lv;
}

// transpose + split W (INV x OUTV) -> Wt (OUTV x INV)
__global__ void splitWt_kernel(const float* __restrict__ W) {
    __shared__ float t[32][33];
    int kbase = blockIdx.y * 32, nbase = blockIdx.x * 32;
    int tx = threadIdx.x, ty = threadIdx.y;
#pragma unroll
    for (int j = 0; j < 32; j += 8)
        t[ty + j][tx] = W[(size_t)(kbase + ty + j) * OUTV + nbase + tx];
    __syncthreads();
#pragma unroll
    for (int j = 0; j < 32; j += 8) {
        int n = nbase + ty + j;
        __nv_bfloat16 h, l;
        split1(t[tx][ty + j], h, l);
        g_Wth[(size_t)n * INV + kbase + tx] = h;
        g_Wtl[(size_t)n * INV + kbase + tx] = l;
    }
}

// ---------------------------------------------------------------------------
// Y = H_v @ W on HMMA core; epilogue writes Yt (transposed) bf16-split
// ---------------------------------------------------------------------------
__global__ __launch_bounds__(256, 2) void ygemm_mma() {
    extern __shared__ char dynsm[];
    uint32_t sb = smem_u32(dynsm);
    float* smC = (float*)dynsm;
    const int tid = threadIdx.x, wid = tid >> 5, lid = tid & 31;

    const int bi = blockIdx.x >> 2, bj = blockIdx.x & 3;   // 32 x 4
    const int row0 = bi * 128, col0 = bj * 128;

    float acc[4][4][4] = {};
    gemm_core(sb, INV / KCH,
              g_Hh + (size_t)row0 * INV, g_Hl + (size_t)row0 * INV, INV,
              g_Wth + (size_t)col0 * INV, g_Wtl + (size_t)col0 * INV, INV, acc);
    __syncthreads();
    store_c(smC, acc);
    __syncthreads();

    // write transposed: Yt[n][k] = Y[k][n], n = col0+cc, k = row0+rbase..+3
    for (int cc = wid; cc < 128; cc += 8) {
        int n = col0 + cc;
        int rbase = lid << 2;
        float y0 = smC[(rbase+0)*129 + cc], y1 = smC[(rbase+1)*129 + cc];
        float y2 = smC[(rbase+2)*129 + cc], y3 = smC[(rbase+3)*129 + cc];
        uint2 hv, lv;
        split_pack4(y0, y1, y2, y3, hv, lv);
        size_t o = (size_t)n * Nn + row0 + rbase;
        *(uint2*)(g_Yth + o) = hv; *(uint2*)(g_Ytl + o) = lv;
    }
}

// ---------------------------------------------------------------------------
// symmetric big GEMM: R5 config (528 CTAs, supergroup order)
// ---------------------------------------------------------------------------
__global__ __launch_bounds__(256, 2) void symgemm_mma(const float* __restrict__ adjv) {
    extern __shared__ char dynsm[];
    uint32_t sb = smem_u32(dynsm);
    float* smC = (float*)dynsm;
    const int tid = threadIdx.x, wid = tid >> 5, lid = tid & 31;

    // decode blockIdx.x -> (bi,bj): 8x8 super-groups over the upper triangle
    int t = blockIdx.x, SI = 0, SJ = 0;
    bool found = false;
    for (SI = 0; SI < NT2/8 && !found; ++SI)
        for (SJ = SI; SJ < NT2/8; ++SJ) {
            int sz = (SI == SJ) ? 36 : 64;
            if (t < sz) { found = true; break; }
            t -= sz;
        }
    --SI;
    int bi, bj;
    if (SI == SJ) {
        int li = 0;
        while (t >= 8 - li) { t -= 8 - li; ++li; }
        bi = SI * 8 + li; bj = SJ * 8 + li + t;
    } else {
        bi = SI * 8 + (t >> 3); bj = SJ * 8 + (t & 7);
    }
    const int row0 = bi * 128, col0 = bj * 128;

    float acc[4][4][4] = {};
    gemm_core(sb, Ee / KCH,
              g_TAh + (size_t)row0 * Ee, g_TAl + (size_t)row0 * Ee, Ee,
              g_TBh + (size_t)col0 * Ee, g_TBl + (size_t)col0 * Ee, Ee, acc);
    __syncthreads();
    store_c(smC, acc);
    __syncthreads();

    for (int rr = wid; rr < 128; rr += 8) {
        int gi = row0 + rr;
        int cbase = lid << 2;
        float m0 = smC[rr*129 + cbase+0], m1 = smC[rr*129 + cbase+1];
        float m2 = smC[rr*129 + cbase+2], m3 = smC[rr*129 + cbase+3];
        if (bi == bj) {
            int jb = rr - cbase;
            if (jb == 0) m0 = 1.f; else if (jb == 1) m1 = 1.f;
            else if (jb == 2) m2 = 1.f; else if (jb == 3) m3 = 1.f;
        }
        const float4 a4 = *(const float4*)&adjv[(size_t)gi * Nn + col0 + cbase];
        uint2 hv, lv;
        split_pack4((m0+1.f)*a4.x, (m1+1.f)*a4.y, (m2+1.f)*a4.z, (m3+1.f)*a4.w, hv, lv);
        size_t o = (size_t)gi * Nn + col0 + cbase;
        *(uint2*)(g_Bh + o) = hv; *(uint2*)(g_Bl + o) = lv;
    }
    if (bi != bj) {
        for (int cc = wid; cc < 128; cc += 8) {
            int gj = col0 + cc;
            int rbase = lid << 2;
            float m0 = smC[(rbase+0)*129 + cc], m1 = smC[(rbase+1)*129 + cc];
            float m2 = smC[(rbase+2)*129 + cc], m3 = smC[(rbase+3)*129 + cc];
            const float4 a4 = *(const float4*)&adjv[(size_t)gj * Nn + row0 + rbase];
            uint2 hv, lv;
            split_pack4((m0+1.f)*a4.x, (m1+1.f)*a4.y, (m2+1.f)*a4.z, (m3+1.f)*a4.w, hv, lv);
            size_t o = (size_t)gj * Nn + row0 + rbase;
            *(uint2*)(g_Bh + o) = hv; *(uint2*)(g_Bl + o) = lv;
        }
    }
}

// ---------------------------------------------------------------------------
// out = 0.5 * B @ Y + bias  (R5 config)
// ---------------------------------------------------------------------------
__global__ __launch_bounds__(256, 2) void outgemm_mma(const float* __restrict__ bias,
                                                      float* __restrict__ outp) {
    extern __shared__ char dynsm[];
    uint32_t sb = smem_u32(dynsm);
    float* smC = (float*)dynsm;
    const int tid = threadIdx.x, wid = tid >> 5, lid = tid & 31;

    const int bi = blockIdx.x >> 2, bj = blockIdx.x & 3;
    const int row0 = bi * 128, col0 = bj * 128;

    float acc[4][4][4] = {};
    gemm_core(sb, Nn / KCH,
              g_Bh + (size_t)row0 * Nn, g_Bl + (size_t)row0 * Nn, Nn,
              g_Yth + (size_t)col0 * Nn, g_Ytl + (size_t)col0 * Nn, Nn, acc);
    __syncthreads();
    store_c(smC, acc);
    __syncthreads();

    for (int rr = wid; rr < 128; rr += 8) {
        int gi = row0 + rr;
        int cbase = lid << 2;
        const float4 b4 = *(const float4*)&bias[col0 + cbase];
        float4 o4 = { 0.5f*smC[rr*129+cbase+0] + b4.x, 0.5f*smC[rr*129+cbase+1] + b4.y,
                      0.5f*smC[rr*129+cbase+2] + b4.z, 0.5f*smC[rr*129+cbase+3] + b4.w };
        *(float4*)&outp[(size_t)gi * OUTV + col0 + cbase] = o4;
    }
}

__global__ void copy_kernel(const float* __restrict__ s, float* __restrict__ d, int n4) {
    int i = blockIdx.x * blockDim.x + threadIdx.x;
    if (i < n4) ((float4*)d)[i] = ((const float4*)s)[i];
}

extern "C" void kernel_launch(void* const* d_in, const int* in_sizes, int n_in,
                              void* d_out, int out_size) {
    const float* H_v   = (const float*)d_in[0];
    const float* H_e   = (const float*)d_in[1];
    const float* adj_v = (const float*)d_in[3];
    const float* T     = (const float*)d_in[4];
    const float* W     = (const float*)d_in[5];
    const float* p     = (const float*)d_in[6];
    const float* bias  = (const float*)d_in[7];
    float* out = (float*)d_out;

    cudaFuncSetAttribute(symgemm_mma, cudaFuncAttributeMaxDynamicSharedMemorySize, DSMEM);
    cudaFuncSetAttribute(outgemm_mma, cudaFuncAttributeMaxDynamicSharedMemorySize, DSMEM);
    cudaFuncSetAttribute(ygemm_mma, cudaFuncAttributeMaxDynamicSharedMemorySize, DSMEM);

    escale_kernel<<<Ee / 8, 256>>>(H_e, p);
    splitT_kernel<<<(int)(((size_t)Nn * Ee / 4) / 256), 256>>>(T);
    splitHv_kernel<<<(int)(((size_t)Nn * INV / 4) / 256), 256>>>(H_v);
    splitWt_kernel<<<dim3(OUTV / 32, INV / 32), dim3(32, 8)>>>(W);
    ygemm_mma<<<128, 256, DSMEM>>>();
    symgemm_mma<<<NTIL, 256, DSMEM>>>(adj_v);
    outgemm_mma<<<128, 256, DSMEM>>>(bias, out);

    if (out_size >= Nn * OUTV + Ee * 128) {
        int n4 = (Ee * 128) / 4;
        copy_kernel<<<(n4 + 255) / 256, 256>>>(H_e, out + (size_t)Nn * OUTV, n4);
    }
}